// round 15
// baseline (speedup 1.0000x reference)
#include <cuda_runtime.h>

// Problem shape (fixed by setup_inputs): B=1, C=32, H=128, W=256, D=48
#define C_ 32
#define H_ 128
#define W_ 256
#define D_ 48
#define HW_  (H_ * W_)
#define DHW_ (D_ * HW_)
#define WCH_ 128              // w-chunk width (2 chunks per row)

// Scratch: vertically pre-lerped y, transposed to [H, W, C].
// ybar[h,w,c] = y[c,y0(h),w]*(1-wy)*my0 + y[c,y1(h),w]*wy*my1
// One bilinear sample then needs only the 2 horizontal corners.
__device__ float g_yT[(size_t)H_ * W_ * C_];

// ---------------------------------------------------------------------------
// Pre-pass: vertical lerp + transpose  y [C,H,W] -> ybar [H,W,C].
// The vertical weights/masks depend only on h = blockIdx.y.
// ---------------------------------------------------------------------------
__global__ void transpose_lerp_y_kernel(const float* __restrict__ y) {
    __shared__ float tile[32][33];
    const int h  = blockIdx.y;
    const int w0 = blockIdx.x * 32;
    const int tx = threadIdx.x;   // 0..31
    const int ty = threadIdx.y;   // 0..7

    // vertical sample coordinate (reference formula)
    const float gy  = (float)h / ((H_ - 1.0f) / 2.0f) - 1.0f;
    const float iy  = ((gy + 1.0f) * (float)H_ - 1.0f) * 0.5f;
    const float fy0 = floorf(iy);
    const float wy  = iy - fy0;
    const int y0i = (int)fy0;
    const int y1i = y0i + 1;
    const float p = (y0i >= 0 && y0i < H_) ? (1.0f - wy) : 0.0f;  // mask folded
    const float q = (y1i >= 0 && y1i < H_) ? wy : 0.0f;
    const int yc0 = min(max(y0i, 0), H_ - 1);
    const int yc1 = min(max(y1i, 0), H_ - 1);

#pragma unroll
    for (int i = 0; i < 32; i += 8) {
        const int c = ty + i;
        const float v0 = y[c * HW_ + yc0 * W_ + w0 + tx];
        const float v1 = y[c * HW_ + yc1 * W_ + w0 + tx];
        tile[c][tx] = v0 * p + v1 * q;
    }
    __syncthreads();
#pragma unroll
    for (int i = 0; i < 32; i += 8)
        g_yT[((size_t)h * W_ + (w0 + ty + i)) * C_ + tx] = tile[tx][ty + i];
}

// ---------------------------------------------------------------------------
// Main kernel: one block per (h, d). 256 threads.
//  Phase 0: thread t computes horizontal weights/offsets for w = t, packed
//           into ONE float4 smem word (wa, wb, off0, off1).
//  Per 128-wide w-chunk:
//   Phase 1: lanes = channels; 2 fully-coalesced LDG.128 per (position,cquad)
//            (corners pre-lerped vertically); scalar STS into swizzled tile.
//   Phase 2: one LDS.128 + one fully coalesced STG.128 per (warp, channel).
//  Left half: straight float4 copy of x broadcast over d.
// ---------------------------------------------------------------------------
__global__ __launch_bounds__(256)
void cost_volume_kernel(const float* __restrict__ x,
                        const float* __restrict__ disp,
                        float* __restrict__ out) {
    const int h = blockIdx.x;
    const int d = blockIdx.y;
    const int t = threadIdx.x;          // 0..255
    const int wp   = t >> 5;            // warp id 0..7
    const int lane = t & 31;

    __shared__ float4 swo[W_];          // (wa, wb, off0, off1) per w      4KB
    __shared__ float  stile[C_ * WCH_]; // [c][w'] swizzled chunk tile    16KB

    // ---------------- Phase 0: horizontal weights & offsets for w = t -----
    {
        const int w = t;
        const float dv    = disp[(d * H_ + h) * W_ + w];
        const float cur_x = (float)w - dv;
        const float gx    = cur_x / ((W_ - 1.0f) / 2.0f) - 1.0f;
        const float ix    = ((gx + 1.0f) * (float)W_ - 1.0f) * 0.5f;
        const float fx0   = floorf(ix);
        const float wx    = ix - fx0;
        const int x0i = (int)fx0;
        const int x1i = x0i + 1;
        const float wa = (x0i >= 0 && x0i < W_) ? (1.0f - wx) : 0.0f;
        const float wb = (x1i >= 0 && x1i < W_) ? wx : 0.0f;
        const int xc0 = min(max(x0i, 0), W_ - 1);
        const int xc1 = min(max(x1i, 0), W_ - 1);
        swo[w] = make_float4(wa, wb,
                             __int_as_float(xc0 * C_),
                             __int_as_float(xc1 * C_));
    }

    // ---------------- Left half: out[c,d,h,:] = x[c,h,:] (float4 copy) ----
    {
        const float* xp = x + h * W_;
        float*       op = out + d * HW_ + h * W_;
#pragma unroll
        for (int rep = 0; rep < 8; rep++) {
            const int idx = rep * 256 + t;
            const int c   = idx >> 6;          // 0..31
            const int w4  = (idx & 63) * 4;    // 0..252
            const float4 xv = *(const float4*)(xp + c * HW_ + w4);
            *(float4*)(op + c * DHW_ + w4) = xv;
        }
    }
    __syncthreads();

    const int sub = lane >> 3;      // 0..3  (position within iter-quad)
    const int cq  = lane & 7;       // 0..7  (channel quad)
    const int cq4 = cq << 2;
    const float* const yrow = g_yT + (size_t)h * W_ * C_;  // this h's ybar row
    float* const outw = out + (size_t)C_ * DHW_ + d * HW_ + h * W_;

#pragma unroll
    for (int ch = 0; ch < 2; ch++) {
        const int wbase = ch * WCH_;

        // -------- Phase 1: 2-corner gathers, lanes = channels -------------
#pragma unroll
        for (int i = 0; i < 4; i++) {
            const int wl = wp * 16 + i * 4 + sub;   // 0..127 within chunk
            const int w  = wbase + wl;
            const float4 wo = swo[w];               // 8-lane broadcast
            const int o0 = __float_as_int(wo.z) + cq4;
            const int o1 = __float_as_int(wo.w) + cq4;

            const float4 v0 = *(const float4*)&yrow[o0];
            const float4 v1 = *(const float4*)&yrow[o1];
            float4 acc;
            acc.x = v0.x * wo.x; acc.y = v0.y * wo.x;
            acc.z = v0.z * wo.x; acc.w = v0.w * wo.x;
            acc.x = fmaf(v1.x, wo.y, acc.x); acc.y = fmaf(v1.y, wo.y, acc.y);
            acc.z = fmaf(v1.z, wo.y, acc.z); acc.w = fmaf(v1.w, wo.y, acc.w);

            // [c][w'] with quad-xor swizzle: w' = wl ^ (cq<<2)
            float* sp = &stile[cq4 * WCH_ + (wl ^ (cq << 2))];
            sp[0 * WCH_] = acc.x;
            sp[1 * WCH_] = acc.y;
            sp[2 * WCH_] = acc.z;
            sp[3 * WCH_] = acc.w;
        }
        __syncthreads();

        // -------- Phase 2: vector read + fully coalesced vector store -----
        {
            float* op = outw + wbase + lane * 4 + wp * DHW_;
            const int l4 = lane * 4;
#pragma unroll
            for (int j = 0; j < 4; j++) {
                const int c   = wp + j * 8;            // 0..31
                const int wsw = l4 ^ ((c >> 2) << 2);
                const float4 v = *(const float4*)&stile[c * WCH_ + wsw];
                *(float4*)op = v;
                op += 8 * DHW_;
            }
        }
        __syncthreads();   // stile reused by next chunk
    }
}

// ---------------------------------------------------------------------------
extern "C" void kernel_launch(void* const* d_in, const int* in_sizes, int n_in,
                              void* d_out, int out_size) {
    (void)in_sizes; (void)n_in; (void)out_size;
    const float* x    = (const float*)d_in[0];
    const float* y    = (const float*)d_in[1];
    const float* disp = (const float*)d_in[2];
    float* out = (float*)d_out;

    dim3 tb(32, 8);
    dim3 tg(W_ / 32, H_);
    transpose_lerp_y_kernel<<<tg, tb>>>(y);

    dim3 grid(H_, D_);                 // one block per (h, d)
    cost_volume_kernel<<<grid, 256>>>(x, disp, out);
}

// round 16
// speedup vs baseline: 1.0069x; 1.0069x over previous
#include <cuda_runtime.h>

// Problem shape (fixed by setup_inputs): B=1, C=32, H=128, W=256, D=48
#define C_ 32
#define H_ 128
#define W_ 256
#define D_ 48
#define HW_  (H_ * W_)
#define DHW_ (D_ * HW_)
#define WCH_ 128              // w-chunk width (2 chunks per row)

// Scratch: vertically pre-lerped y, transposed to [H, W, C].
// ybar[h,w,c] = y[c,y0(h),w]*(1-wy)*my0 + y[c,y1(h),w]*wy*my1
// One bilinear sample then needs only the 2 horizontal corners.
__device__ float g_yT[(size_t)H_ * W_ * C_];

// ---------------------------------------------------------------------------
// Pre-pass: vertical lerp + transpose  y [C,H,W] -> ybar [H,W,C].
// The vertical weights/masks depend only on h = blockIdx.y.
// ---------------------------------------------------------------------------
__global__ void transpose_lerp_y_kernel(const float* __restrict__ y) {
    __shared__ float tile[32][33];
    const int h  = blockIdx.y;
    const int w0 = blockIdx.x * 32;
    const int tx = threadIdx.x;   // 0..31
    const int ty = threadIdx.y;   // 0..7

    // vertical sample coordinate (reference formula)
    const float gy  = (float)h / ((H_ - 1.0f) / 2.0f) - 1.0f;
    const float iy  = ((gy + 1.0f) * (float)H_ - 1.0f) * 0.5f;
    const float fy0 = floorf(iy);
    const float wy  = iy - fy0;
    const int y0i = (int)fy0;
    const int y1i = y0i + 1;
    const float p = (y0i >= 0 && y0i < H_) ? (1.0f - wy) : 0.0f;  // mask folded
    const float q = (y1i >= 0 && y1i < H_) ? wy : 0.0f;
    const int yc0 = min(max(y0i, 0), H_ - 1);
    const int yc1 = min(max(y1i, 0), H_ - 1);

#pragma unroll
    for (int i = 0; i < 32; i += 8) {
        const int c = ty + i;
        const float v0 = y[c * HW_ + yc0 * W_ + w0 + tx];
        const float v1 = y[c * HW_ + yc1 * W_ + w0 + tx];
        tile[c][tx] = v0 * p + v1 * q;
    }
    __syncthreads();
#pragma unroll
    for (int i = 0; i < 32; i += 8)
        g_yT[((size_t)h * W_ + (w0 + ty + i)) * C_ + tx] = tile[tx][ty + i];
}

// ---------------------------------------------------------------------------
// Main kernel: one block per (h, d). 256 threads.
//  Phase 0: thread t computes horizontal weights/offsets for w = t, packed
//           into ONE float4 smem word (wa, wb, off0, off1).
//  Per 128-wide w-chunk:
//   Phase 1: lanes = channels; 2 fully-coalesced LDG.128 per (position,cquad)
//            (corners pre-lerped vertically); scalar STS into swizzled tile.
//   Phase 2: one LDS.128 + one fully coalesced STG.128 per (warp, channel).
//  Left half: straight float4 copy of x broadcast over d.
// ---------------------------------------------------------------------------
__global__ __launch_bounds__(256)
void cost_volume_kernel(const float* __restrict__ x,
                        const float* __restrict__ disp,
                        float* __restrict__ out) {
    const int h = blockIdx.x;
    const int d = blockIdx.y;
    const int t = threadIdx.x;          // 0..255
    const int wp   = t >> 5;            // warp id 0..7
    const int lane = t & 31;

    __shared__ float4 swo[W_];          // (wa, wb, off0, off1) per w      4KB
    __shared__ float  stile[C_ * WCH_]; // [c][w'] swizzled chunk tile    16KB

    // ---------------- Phase 0: horizontal weights & offsets for w = t -----
    {
        const int w = t;
        const float dv    = disp[(d * H_ + h) * W_ + w];
        const float cur_x = (float)w - dv;
        const float gx    = cur_x / ((W_ - 1.0f) / 2.0f) - 1.0f;
        const float ix    = ((gx + 1.0f) * (float)W_ - 1.0f) * 0.5f;
        const float fx0   = floorf(ix);
        const float wx    = ix - fx0;
        const int x0i = (int)fx0;
        const int x1i = x0i + 1;
        const float wa = (x0i >= 0 && x0i < W_) ? (1.0f - wx) : 0.0f;
        const float wb = (x1i >= 0 && x1i < W_) ? wx : 0.0f;
        const int xc0 = min(max(x0i, 0), W_ - 1);
        const int xc1 = min(max(x1i, 0), W_ - 1);
        swo[w] = make_float4(wa, wb,
                             __int_as_float(xc0 * C_),
                             __int_as_float(xc1 * C_));
    }

    // ---------------- Left half: out[c,d,h,:] = x[c,h,:] (float4 copy) ----
    {
        const float* xp = x + h * W_;
        float*       op = out + d * HW_ + h * W_;
#pragma unroll
        for (int rep = 0; rep < 8; rep++) {
            const int idx = rep * 256 + t;
            const int c   = idx >> 6;          // 0..31
            const int w4  = (idx & 63) * 4;    // 0..252
            const float4 xv = *(const float4*)(xp + c * HW_ + w4);
            *(float4*)(op + c * DHW_ + w4) = xv;
        }
    }
    __syncthreads();

    const int sub = lane >> 3;      // 0..3  (position within iter-quad)
    const int cq  = lane & 7;       // 0..7  (channel quad)
    const int cq4 = cq << 2;
    const float* const yrow = g_yT + (size_t)h * W_ * C_;  // this h's ybar row
    float* const outw = out + (size_t)C_ * DHW_ + d * HW_ + h * W_;

#pragma unroll
    for (int ch = 0; ch < 2; ch++) {
        const int wbase = ch * WCH_;

        // -------- Phase 1: 2-corner gathers, lanes = channels -------------
#pragma unroll
        for (int i = 0; i < 4; i++) {
            const int wl = wp * 16 + i * 4 + sub;   // 0..127 within chunk
            const int w  = wbase + wl;
            const float4 wo = swo[w];               // 8-lane broadcast
            const int o0 = __float_as_int(wo.z) + cq4;
            const int o1 = __float_as_int(wo.w) + cq4;

            const float4 v0 = *(const float4*)&yrow[o0];
            const float4 v1 = *(const float4*)&yrow[o1];
            float4 acc;
            acc.x = v0.x * wo.x; acc.y = v0.y * wo.x;
            acc.z = v0.z * wo.x; acc.w = v0.w * wo.x;
            acc.x = fmaf(v1.x, wo.y, acc.x); acc.y = fmaf(v1.y, wo.y, acc.y);
            acc.z = fmaf(v1.z, wo.y, acc.z); acc.w = fmaf(v1.w, wo.y, acc.w);

            // [c][w'] with quad-xor swizzle: w' = wl ^ (cq<<2)
            float* sp = &stile[cq4 * WCH_ + (wl ^ (cq << 2))];
            sp[0 * WCH_] = acc.x;
            sp[1 * WCH_] = acc.y;
            sp[2 * WCH_] = acc.z;
            sp[3 * WCH_] = acc.w;
        }
        __syncthreads();

        // -------- Phase 2: vector read + fully coalesced vector store -----
        {
            float* op = outw + wbase + lane * 4 + wp * DHW_;
            const int l4 = lane * 4;
#pragma unroll
            for (int j = 0; j < 4; j++) {
                const int c   = wp + j * 8;            // 0..31
                const int wsw = l4 ^ ((c >> 2) << 2);
                const float4 v = *(const float4*)&stile[c * WCH_ + wsw];
                *(float4*)op = v;
                op += 8 * DHW_;
            }
        }
        __syncthreads();   // stile reused by next chunk
    }
}

// ---------------------------------------------------------------------------
extern "C" void kernel_launch(void* const* d_in, const int* in_sizes, int n_in,
                              void* d_out, int out_size) {
    (void)in_sizes; (void)n_in; (void)out_size;
    const float* x    = (const float*)d_in[0];
    const float* y    = (const float*)d_in[1];
    const float* disp = (const float*)d_in[2];
    float* out = (float*)d_out;

    dim3 tb(32, 8);
    dim3 tg(W_ / 32, H_);
    transpose_lerp_y_kernel<<<tg, tb>>>(y);

    dim3 grid(H_, D_);                 // one block per (h, d)
    cost_volume_kernel<<<grid, 256>>>(x, disp, out);
}